// round 2
// baseline (speedup 1.0000x reference)
#include <cuda_runtime.h>
#include <math.h>

#define BB 2
#define LL 384
#define DD 256
#define HH 8
#define DHH 32

// Scratch (device globals — no allocation allowed)
__device__ float g_KP[BB*HH*LL*DHH];   // [b][h][l][dh]
__device__ float g_VP[BB*HH*LL*DHH];   // [b][h][l][dh]
__device__ float g_QU[BB*LL*DD];       // [b][l][h*32+dh]  (q + u)
__device__ float g_QV[BB*LL*DD];       // [b][l][h*32+dh]  (q + v)
__device__ float g_W [BB*LL*HH*DD];    // [b][q][h][d]

// ---------------------------------------------------------------------------
// Kernel 1: fused Q/K/V projections.  out = X @ W.T + b  (M=768, N=256, K=256)
// 64x64 tile, 256 threads, 4x4 per thread. grid (12, 4, 3)
// ---------------------------------------------------------------------------
__global__ void __launch_bounds__(256) proj_kernel(
    const float* __restrict__ key,   const float* __restrict__ query,
    const float* __restrict__ value,
    const float* __restrict__ Wk, const float* __restrict__ bk,
    const float* __restrict__ Wq, const float* __restrict__ bq,
    const float* __restrict__ Wv, const float* __restrict__ bv,
    const float* __restrict__ u,  const float* __restrict__ vvec)
{
    const int z = blockIdx.z;
    const float* X    = (z == 0) ? key : (z == 1) ? query : value;
    const float* Wt   = (z == 0) ? Wk  : (z == 1) ? Wq    : Wv;
    const float* bias = (z == 0) ? bk  : (z == 1) ? bq    : bv;

    const int m0 = blockIdx.x * 64;
    const int n0 = blockIdx.y * 64;
    const int tid = threadIdx.x;
    const int tx = tid % 16, ty = tid / 16;

    __shared__ float a_sm[64 * 17];      // [row][k], pad 17
    __shared__ float b_sm[16 * 68];      // [k][col], pad 68

    float acc[4][4] = {};

    for (int kt = 0; kt < DD; kt += 16) {
        // A tile: 64 rows x 16 k
        {
            int r = tid / 4, c = (tid % 4) * 4;
            float4 va = *(const float4*)(X + (m0 + r) * DD + kt + c);
            float* dst = a_sm + r * 17 + c;
            dst[0] = va.x; dst[1] = va.y; dst[2] = va.z; dst[3] = va.w;
        }
        // B tile (transposed into [k][col]): cols are W rows (output features)
        {
            int r = tid / 4, c = (tid % 4) * 4;
            float4 vb = *(const float4*)(Wt + (n0 + r) * DD + kt + c);
            b_sm[(c + 0) * 68 + r] = vb.x;
            b_sm[(c + 1) * 68 + r] = vb.y;
            b_sm[(c + 2) * 68 + r] = vb.z;
            b_sm[(c + 3) * 68 + r] = vb.w;
        }
        __syncthreads();
        #pragma unroll
        for (int k = 0; k < 16; k++) {
            float a0 = a_sm[(ty * 4 + 0) * 17 + k];
            float a1 = a_sm[(ty * 4 + 1) * 17 + k];
            float a2 = a_sm[(ty * 4 + 2) * 17 + k];
            float a3 = a_sm[(ty * 4 + 3) * 17 + k];
            float4 bf = *(const float4*)(b_sm + k * 68 + tx * 4);
            acc[0][0] += a0 * bf.x; acc[0][1] += a0 * bf.y; acc[0][2] += a0 * bf.z; acc[0][3] += a0 * bf.w;
            acc[1][0] += a1 * bf.x; acc[1][1] += a1 * bf.y; acc[1][2] += a1 * bf.z; acc[1][3] += a1 * bf.w;
            acc[2][0] += a2 * bf.x; acc[2][1] += a2 * bf.y; acc[2][2] += a2 * bf.z; acc[2][3] += a2 * bf.w;
            acc[3][0] += a3 * bf.x; acc[3][1] += a3 * bf.y; acc[3][2] += a3 * bf.z; acc[3][3] += a3 * bf.w;
        }
        __syncthreads();
    }

    #pragma unroll
    for (int i = 0; i < 4; i++) {
        int n = m0 + ty * 4 + i;
        int b = n / LL, l = n % LL;
        #pragma unroll
        for (int j = 0; j < 4; j++) {
            int jc = n0 + tx * 4 + j;
            float val = acc[i][j] + bias[jc];
            int h = jc / DHH, dh = jc % DHH;
            if (z == 0) {
                g_KP[((b * HH + h) * LL + l) * DHH + dh] = val;
            } else if (z == 2) {
                g_VP[((b * HH + h) * LL + l) * DHH + dh] = val;
            } else {
                g_QU[n * DD + jc] = val + u[jc];
                g_QV[n * DD + jc] = val + vvec[jc];
            }
        }
    }
}

// ---------------------------------------------------------------------------
// Kernel 2: W[b,q,h,:] = sum_dh QV[b,q,h,dh] * Wr[h*32+dh, :]
// per-head GEMM [768 x 32] @ [32 x 256]. 64x64 tile. grid (12, 4, 8)
// ---------------------------------------------------------------------------
__global__ void __launch_bounds__(256) w_kernel(const float* __restrict__ Wr)
{
    const int h  = blockIdx.z;
    const int m0 = blockIdx.x * 64;   // bq tile
    const int n0 = blockIdx.y * 64;   // d tile
    const int tid = threadIdx.x;
    const int tx = tid % 16, ty = tid / 16;

    __shared__ float a_sm[64 * 33];   // [row][k], pad 33
    __shared__ float b_sm[32 * 68];   // [k][col], pad 68

    // A: QV rows, head slice (64 x 32)
    {
        int r = tid / 4, cb = (tid % 4) * 8;
        #pragma unroll
        for (int cc = 0; cc < 8; cc += 4) {
            float4 va = *(const float4*)(g_QV + (m0 + r) * DD + h * DHH + cb + cc);
            float* dst = a_sm + r * 33 + cb + cc;
            dst[0] = va.x; dst[1] = va.y; dst[2] = va.z; dst[3] = va.w;
        }
    }
    // B: Wr head rows (32 x 64), stored [k][col]
    {
        int k = tid / 8, cb = (tid % 8) * 8;
        #pragma unroll
        for (int cc = 0; cc < 8; cc += 4) {
            float4 vb = *(const float4*)(Wr + (h * DHH + k) * DD + n0 + cb + cc);
            *(float4*)(b_sm + k * 68 + cb + cc) = vb;
        }
    }
    __syncthreads();

    float acc[4][4] = {};
    #pragma unroll
    for (int k = 0; k < 32; k++) {
        float a0 = a_sm[(ty * 4 + 0) * 33 + k];
        float a1 = a_sm[(ty * 4 + 1) * 33 + k];
        float a2 = a_sm[(ty * 4 + 2) * 33 + k];
        float a3 = a_sm[(ty * 4 + 3) * 33 + k];
        float4 bf = *(const float4*)(b_sm + k * 68 + tx * 4);
        acc[0][0] += a0 * bf.x; acc[0][1] += a0 * bf.y; acc[0][2] += a0 * bf.z; acc[0][3] += a0 * bf.w;
        acc[1][0] += a1 * bf.x; acc[1][1] += a1 * bf.y; acc[1][2] += a1 * bf.z; acc[1][3] += a1 * bf.w;
        acc[2][0] += a2 * bf.x; acc[2][1] += a2 * bf.y; acc[2][2] += a2 * bf.z; acc[2][3] += a2 * bf.w;
        acc[3][0] += a3 * bf.x; acc[3][1] += a3 * bf.y; acc[3][2] += a3 * bf.z; acc[3][3] += a3 * bf.w;
    }

    #pragma unroll
    for (int i = 0; i < 4; i++) {
        int bq = m0 + ty * 4 + i;
        #pragma unroll
        for (int j = 0; j < 4; j++) {
            g_W[((size_t)bq * HH + h) * DD + n0 + tx * 4 + j] = acc[i][j];
        }
    }
}

// ---------------------------------------------------------------------------
// Kernel 3: main attention. One block per (q, b), warp = head.
// Streams pos[b,q,k,:] coalesced; W-slice in registers; fused A_C term;
// warp-private softmax; attn @ V.
// ---------------------------------------------------------------------------
__global__ void __launch_bounds__(256) attn_kernel(
    const float* __restrict__ pos,
    const float* __restrict__ key_mask,
    const float* __restrict__ br,
    float* __restrict__ out)
{
    const int q = blockIdx.x, b = blockIdx.y;
    const int tid = threadIdx.x;
    const int h = tid / 32, lane = tid % 32;

    __shared__ float sc[HH][LL];
    __shared__ float pm[LL];

    // mask penalty (all-ones mask in this dataset, but keep it general)
    for (int k = tid; k < LL; k += 256)
        pm[k] = (1.0f - key_mask[b * LL + k]) * 1e15f;

    // W slice for this (b,q,h): 8 floats per lane, in registers
    const float* wrow = g_W + (((size_t)(b * LL + q)) * HH + h) * DD + lane * 8;
    const float4 wa = *(const float4*)(wrow);
    const float4 wb = *(const float4*)(wrow + 4);

    const float quv = g_QU[(b * LL + q) * DD + h * DHH + lane];
    const float qvv = g_QV[(b * LL + q) * DD + h * DHH + lane];

    // cc = (q+v) . br  (warp reduce)
    float ccp = qvv * br[h * DHH + lane];
    #pragma unroll
    for (int off = 16; off; off >>= 1)
        ccp += __shfl_xor_sync(0xffffffffu, ccp, off);

    const float scale = 0.17677669529663687f;  // 1/sqrt(32)
    const float* posb = pos + ((size_t)(b * LL + q)) * LL * DD;
    const float* kpb  = g_KP + ((size_t)(b * HH + h)) * LL * DHH;
    __syncthreads();

    // scores: B_D (pos . W) fused with A_C (kp . qu)
    #pragma unroll 4
    for (int k = 0; k < LL; k++) {
        const float* pr = posb + k * DD + lane * 8;
        float4 p0 = *(const float4*)(pr);
        float4 p1 = *(const float4*)(pr + 4);
        float kp = kpb[k * DHH + lane];
        float part = kp * quv;
        part += p0.x * wa.x + p0.y * wa.y + p0.z * wa.z + p0.w * wa.w;
        part += p1.x * wb.x + p1.y * wb.y + p1.z * wb.z + p1.w * wb.w;
        #pragma unroll
        for (int off = 16; off; off >>= 1)
            part += __shfl_xor_sync(0xffffffffu, part, off);
        if (lane == 0)
            sc[h][k] = (part + ccp) * scale - pm[k];
    }
    __syncwarp();

    // softmax over k (warp-private row)
    float m = -1e30f;
    for (int k = lane; k < LL; k += 32) m = fmaxf(m, sc[h][k]);
    #pragma unroll
    for (int off = 16; off; off >>= 1)
        m = fmaxf(m, __shfl_xor_sync(0xffffffffu, m, off));
    float s = 0.0f;
    for (int k = lane; k < LL; k += 32) {
        float e = __expf(sc[h][k] - m);
        sc[h][k] = e;
        s += e;
    }
    #pragma unroll
    for (int off = 16; off; off >>= 1)
        s += __shfl_xor_sync(0xffffffffu, s, off);
    const float rinv = 1.0f / s;
    __syncwarp();

    // out = attn @ V
    float acc = 0.0f;
    const float* vp = g_VP + ((size_t)(b * HH + h)) * LL * DHH + lane;
    #pragma unroll 4
    for (int k = 0; k < LL; k++)
        acc += sc[h][k] * vp[k * DHH];

    out[(b * LL + q) * DD + h * DHH + lane] = acc * rinv;
}

// ---------------------------------------------------------------------------
extern "C" void kernel_launch(void* const* d_in, const int* in_sizes, int n_in,
                              void* d_out, int out_size)
{
    const float* key      = (const float*)d_in[0];
    const float* query    = (const float*)d_in[1];
    const float* value    = (const float*)d_in[2];
    const float* pos      = (const float*)d_in[3];
    const float* key_mask = (const float*)d_in[4];
    const float* Wk = (const float*)d_in[5];
    const float* bk = (const float*)d_in[6];
    const float* Wq = (const float*)d_in[7];
    const float* bq = (const float*)d_in[8];
    const float* Wv = (const float*)d_in[9];
    const float* bv = (const float*)d_in[10];
    const float* Wr = (const float*)d_in[11];
    const float* br = (const float*)d_in[12];
    const float* u  = (const float*)d_in[13];
    const float* v  = (const float*)d_in[14];
    float* out = (float*)d_out;

    proj_kernel<<<dim3(12, 4, 3), 256>>>(key, query, value, Wk, bk, Wq, bq, Wv, bv, u, v);
    w_kernel<<<dim3(12, 4, 8), 256>>>(Wr);
    attn_kernel<<<dim3(LL, BB), 256>>>(pos, key_mask, br, out);
}